// round 1
// baseline (speedup 1.0000x reference)
#include <cuda_runtime.h>
#include <math.h>

#define NN 131072
#define EE 262144
#define DD 128
#define RR 128
#define TT 32
#define KMSG 416      // 2D + R + T
#define WPAD 420      // row stride for W_msg in smem (420 % 32 == 4 -> conflict-free)
#define EV 8          // events per W pass
#define HALF 148      // blocks per message side
#define GK 128
#define GP 132        // row stride for GRU W in smem
#define GOUT 384
#define NODES 8       // nodes per W pass in GRU kernels

// -------- device scratch (no allocation allowed) --------
__device__ float g_sums[(size_t)NN * DD];   // 64 MB
__device__ float g_cnt[NN];
__device__ int   g_tmax[NN];
__device__ float g_gi[(size_t)NN * GOUT];   // 192 MB

// ============================================================
// init: zero the scatter buffers
// ============================================================
__global__ void k_init() {
    size_t i = (size_t)blockIdx.x * blockDim.x + threadIdx.x;
    size_t stride = (size_t)gridDim.x * blockDim.x;
    float4* s4 = (float4*)g_sums;
    size_t n4 = (size_t)NN * DD / 4;
    for (size_t idx = i; idx < n4; idx += stride) s4[idx] = make_float4(0.f, 0.f, 0.f, 0.f);
    for (size_t idx = i; idx < NN; idx += stride) { g_cnt[idx] = 0.f; g_tmax[idx] = 0; }
}

// ============================================================
// message MLPs + scatter.
// blockIdx.x < HALF  : source-side messages (key = src, W_msg_s)
// blockIdx.x >= HALF : dest-side messages  (key = dst, W_msg_d)
// Per block: W (128x416, padded) resident in smem; stream EV events per pass.
// ============================================================
__global__ void __launch_bounds__(128, 1) k_msg(
    const float* __restrict__ mem, const float* __restrict__ raw,
    const float* __restrict__ tw,  const float* __restrict__ tb,
    const float* __restrict__ Ws,  const float* __restrict__ bs,
    const float* __restrict__ Wd,  const float* __restrict__ bd,
    const int* __restrict__ src, const int* __restrict__ dst,
    const int* __restrict__ tt,  const int* __restrict__ lu)
{
    extern __shared__ float sh[];
    float* shW = sh;                    // 128 * WPAD
    float* shX = sh + 128 * WPAD;       // EV * WPAD (reused as msg staging)
    __shared__ int s_key[EV];
    __shared__ int s_t[EV];
    __shared__ int s_valid[EV];

    const int tid  = threadIdx.x;
    const int side = (blockIdx.x >= HALF) ? 1 : 0;
    const int bid  = side ? (blockIdx.x - HALF) : blockIdx.x;
    const float* W = side ? Wd : Ws;
    const float bias = side ? bd[tid] : bs[tid];

    // load W into smem with padded rows
    for (int idx = tid; idx < 128 * KMSG; idx += 128)
        shW[(idx / KMSG) * WPAD + (idx % KMSG)] = W[idx];
    __syncthreads();

    for (int e0 = bid * EV; e0 < EE; e0 += HALF * EV) {
        // ---- gather x = [mem_a, mem_b, raw, t_enc] per event ----
        #pragma unroll
        for (int ev = 0; ev < EV; ev++) {
            int e = e0 + ev;
            bool valid = (e < EE);
            if (tid == 0) s_valid[ev] = valid ? 1 : 0;
            if (!valid) continue;
            int vs = src[e], vd = dst[e];
            int a = side ? vd : vs;   // key node (message owner, time key)
            int b = side ? vs : vd;
            if (tid == 0) { s_key[ev] = a; s_t[ev] = tt[e]; }
            float* x = shX + ev * WPAD;
            x[tid]       = mem[(size_t)a * DD + tid];
            x[128 + tid] = mem[(size_t)b * DD + tid];
            x[256 + tid] = raw[(size_t)e * RR + tid];
            if (tid < TT) {
                // replicate reference fp32 arg exactly, then reduce in double
                float trel = __fsub_rn((float)tt[e], (float)lu[a]);
                float arg  = __fadd_rn(__fmul_rn(trel, tw[tid]), tb[tid]);
                double d  = (double)arg;
                double kq = rint(d * 0.15915494309189535);
                double rd = d - kq * 6.283185307179586;
                x[384 + tid] = cosf((float)rd);
            }
        }
        __syncthreads();

        // ---- GEMV: row = tid, EV events per W read ----
        float acc[EV];
        #pragma unroll
        for (int ev = 0; ev < EV; ev++) acc[ev] = 0.f;
        const float4* wr = (const float4*)(shW + tid * WPAD);
        const float4* xp = (const float4*)shX;
        #pragma unroll 4
        for (int k = 0; k < KMSG / 4; k++) {
            float4 w = wr[k];
            #pragma unroll
            for (int ev = 0; ev < EV; ev++) {
                float4 xv = xp[ev * (WPAD / 4) + k];
                acc[ev] = fmaf(w.x, xv.x, acc[ev]);
                acc[ev] = fmaf(w.y, xv.y, acc[ev]);
                acc[ev] = fmaf(w.z, xv.z, acc[ev]);
                acc[ev] = fmaf(w.w, xv.w, acc[ev]);
            }
        }
        __syncthreads();

        // ---- stage relu(msg) in smem, scatter as float4 atomics ----
        float* shM = shX;
        #pragma unroll
        for (int ev = 0; ev < EV; ev++)
            shM[ev * DD + tid] = fmaxf(acc[ev] + bias, 0.f);
        __syncthreads();

        for (int idx = tid; idx < EV * 32; idx += 128) {
            int ev = idx >> 5, j = idx & 31;
            if (s_valid[ev]) {
                float4 v = *(const float4*)(shM + ev * DD + j * 4);
                atomicAdd((float4*)&g_sums[(size_t)s_key[ev] * DD + j * 4], v);
            }
        }
        if (tid < EV && s_valid[tid]) {
            atomicAdd(&g_cnt[s_key[tid]], 1.0f);
            atomicMax(&g_tmax[s_key[tid]], s_t[tid]);
        }
        __syncthreads();
    }
}

// ============================================================
// gi = aggr @ W_ih^T + b_ih   (aggr computed on the fly from sums/cnt)
// ============================================================
__global__ void __launch_bounds__(GOUT, 1) k_gi(
    const float* __restrict__ Wih, const float* __restrict__ bih)
{
    extern __shared__ float sh[];
    float* shW = sh;                 // GOUT * GP
    float* shX = sh + GOUT * GP;     // NODES * GK
    const int tid = threadIdx.x;

    for (int idx = tid; idx < GOUT * GK; idx += GOUT)
        shW[(idx / GK) * GP + (idx % GK)] = Wih[idx];
    const float bias = bih[tid];
    __syncthreads();

    for (int n0 = blockIdx.x * NODES; n0 < NN; n0 += gridDim.x * NODES) {
        for (int i = tid; i < NODES * GK; i += GOUT) {
            int node = i >> 7, d = i & 127;
            int n = n0 + node;
            float v = 0.f;
            if (n < NN) {
                float c = g_cnt[n];
                v = g_sums[(size_t)n * DD + d] / fmaxf(c, 1.0f);
            }
            shX[node * GK + d] = v;
        }
        __syncthreads();

        float acc[NODES];
        #pragma unroll
        for (int j = 0; j < NODES; j++) acc[j] = 0.f;
        const float4* wr = (const float4*)(shW + tid * GP);
        const float4* xp = (const float4*)shX;
        #pragma unroll 8
        for (int k = 0; k < GK / 4; k++) {
            float4 w = wr[k];
            #pragma unroll
            for (int j = 0; j < NODES; j++) {
                float4 xv = xp[j * (GK / 4) + k];
                acc[j] = fmaf(w.x, xv.x, acc[j]);
                acc[j] = fmaf(w.y, xv.y, acc[j]);
                acc[j] = fmaf(w.z, xv.z, acc[j]);
                acc[j] = fmaf(w.w, xv.w, acc[j]);
            }
        }
        #pragma unroll
        for (int j = 0; j < NODES; j++) {
            int n = n0 + j;
            if (n < NN) g_gi[(size_t)n * GOUT + tid] = acc[j] + bias;
        }
        __syncthreads();
    }
}

// ============================================================
// gh = memory @ W_hh^T + b_hh, then GRU combine -> new_memory
// ============================================================
__global__ void __launch_bounds__(GOUT, 1) k_out(
    const float* __restrict__ mem, const float* __restrict__ Whh,
    const float* __restrict__ bhh, float* __restrict__ out)
{
    extern __shared__ float sh[];
    float* shW = sh;                          // GOUT * GP
    float* shM = sh + GOUT * GP;              // NODES * GK
    float* shG = shM + NODES * GK;            // NODES * GOUT
    const int tid = threadIdx.x;

    for (int idx = tid; idx < GOUT * GK; idx += GOUT)
        shW[(idx / GK) * GP + (idx % GK)] = Whh[idx];
    const float bias = bhh[tid];
    __syncthreads();

    for (int n0 = blockIdx.x * NODES; n0 < NN; n0 += gridDim.x * NODES) {
        for (int i = tid; i < NODES * GK; i += GOUT) {
            int node = i >> 7, d = i & 127;
            int n = n0 + node;
            shM[node * GK + d] = (n < NN) ? mem[(size_t)n * GK + d] : 0.f;
        }
        __syncthreads();

        float acc[NODES];
        #pragma unroll
        for (int j = 0; j < NODES; j++) acc[j] = 0.f;
        const float4* wr = (const float4*)(shW + tid * GP);
        const float4* xp = (const float4*)shM;
        #pragma unroll 8
        for (int k = 0; k < GK / 4; k++) {
            float4 w = wr[k];
            #pragma unroll
            for (int j = 0; j < NODES; j++) {
                float4 xv = xp[j * (GK / 4) + k];
                acc[j] = fmaf(w.x, xv.x, acc[j]);
                acc[j] = fmaf(w.y, xv.y, acc[j]);
                acc[j] = fmaf(w.z, xv.z, acc[j]);
                acc[j] = fmaf(w.w, xv.w, acc[j]);
            }
        }
        #pragma unroll
        for (int j = 0; j < NODES; j++)
            shG[j * GOUT + tid] = acc[j] + bias;
        __syncthreads();

        for (int i = tid; i < NODES * GK; i += GOUT) {
            int node = i >> 7, d = i & 127;
            int n = n0 + node;
            if (n < NN) {
                size_t gb = (size_t)n * GOUT;
                float ir = g_gi[gb + d], iz = g_gi[gb + 128 + d], inn = g_gi[gb + 256 + d];
                float hr = shG[node * GOUT + d];
                float hz = shG[node * GOUT + 128 + d];
                float hn = shG[node * GOUT + 256 + d];
                float rg = 1.f / (1.f + expf(-(ir + hr)));
                float zg = 1.f / (1.f + expf(-(iz + hz)));
                float ng = tanhf(inn + rg * hn);
                out[(size_t)n * GK + d] = (1.f - zg) * ng + zg * shM[node * GK + d];
            }
        }
        __syncthreads();
    }
}

// ============================================================
// new_last_update (reference: where(cnt>0, segment_max(t), 0))
// ============================================================
__global__ void k_lu(float* __restrict__ out) {
    int i = blockIdx.x * blockDim.x + threadIdx.x;
    if (i < NN)
        out[(size_t)NN * DD + i] = (g_cnt[i] > 0.f) ? (float)g_tmax[i] : 0.f;
}

// ============================================================
extern "C" void kernel_launch(void* const* d_in, const int* in_sizes, int n_in,
                              void* d_out, int out_size)
{
    const float* mem = (const float*)d_in[0];
    const float* raw = (const float*)d_in[1];
    const float* tw  = (const float*)d_in[2];
    const float* tb  = (const float*)d_in[3];
    const float* Ws  = (const float*)d_in[4];
    const float* bs  = (const float*)d_in[5];
    const float* Wd  = (const float*)d_in[6];
    const float* bd  = (const float*)d_in[7];
    const float* Wih = (const float*)d_in[8];
    const float* Whh = (const float*)d_in[9];
    const float* bih = (const float*)d_in[10];
    const float* bhh = (const float*)d_in[11];
    const int* src = (const int*)d_in[12];
    const int* dst = (const int*)d_in[13];
    const int* tt  = (const int*)d_in[14];
    const int* lu  = (const int*)d_in[15];
    float* out = (float*)d_out;

    size_t smem_msg = (size_t)(128 * WPAD + EV * WPAD) * sizeof(float);          // 228480
    size_t smem_gi  = (size_t)(GOUT * GP + NODES * GK) * sizeof(float);          // 206848
    size_t smem_out = (size_t)(GOUT * GP + NODES * GK + NODES * GOUT) * sizeof(float); // 219136

    cudaFuncSetAttribute(k_msg, cudaFuncAttributeMaxDynamicSharedMemorySize, (int)smem_msg);
    cudaFuncSetAttribute(k_gi,  cudaFuncAttributeMaxDynamicSharedMemorySize, (int)smem_gi);
    cudaFuncSetAttribute(k_out, cudaFuncAttributeMaxDynamicSharedMemorySize, (int)smem_out);

    k_init<<<2048, 256>>>();
    k_msg<<<2 * HALF, 128, smem_msg>>>(mem, raw, tw, tb, Ws, bs, Wd, bd, src, dst, tt, lu);
    k_gi <<<HALF, GOUT, smem_gi>>>(Wih, bih);
    k_out<<<HALF, GOUT, smem_out>>>(mem, Whh, bhh, out);
    if (out_size >= NN * DD + NN)
        k_lu<<<(NN + 255) / 256, 256>>>(out);
}

// round 2
// speedup vs baseline: 1.5481x; 1.5481x over previous
#include <cuda_runtime.h>
#include <math.h>

#define NN 131072
#define EE 262144
#define DD 128
#define RR 128
#define TT 32
#define KMSG 416      // 2D + R + T
#define WPAD 420      // smem row stride for W_msg (420 % 32 == 4 -> conflict-free LDS.128)
#define EV 8          // events per W pass
#define HALF 148      // blocks per message side
#define KH 52         // float4s per K half (208 floats)
#define GK 128
#define GP 132        // row stride for GRU W in smem
#define GOUT 384
#define NODES_GI 16
#define NODES_OUT 8

// -------- device scratch (no allocation allowed) --------
__device__ float g_sums[(size_t)NN * DD];   // 64 MB
__device__ float g_cnt[NN];
__device__ int   g_tmax[NN];
__device__ float g_gi[(size_t)NN * GOUT];   // 192 MB

// ============================================================
// init: zero the scatter buffers
// ============================================================
__global__ void k_init() {
    size_t i = (size_t)blockIdx.x * blockDim.x + threadIdx.x;
    size_t stride = (size_t)gridDim.x * blockDim.x;
    float4* s4 = (float4*)g_sums;
    size_t n4 = (size_t)NN * DD / 4;
    for (size_t idx = i; idx < n4; idx += stride) s4[idx] = make_float4(0.f, 0.f, 0.f, 0.f);
    for (size_t idx = i; idx < NN; idx += stride) { g_cnt[idx] = 0.f; g_tmax[idx] = 0; }
}

// ============================================================
// message MLPs + scatter. 256 threads: 2-way split-K.
//   tid & 127  = output row
//   tid >> 7   = K half (0: k[0,208), 1: k[208,416))
// blockIdx.x < HALF : source-side (key=src, W_msg_s); else dest-side.
// ============================================================
__global__ void __launch_bounds__(256, 1) k_msg(
    const float* __restrict__ mem, const float* __restrict__ raw,
    const float* __restrict__ tw,  const float* __restrict__ tb,
    const float* __restrict__ Ws,  const float* __restrict__ bs,
    const float* __restrict__ Wd,  const float* __restrict__ bd,
    const int* __restrict__ src, const int* __restrict__ dst,
    const int* __restrict__ tt,  const int* __restrict__ lu)
{
    extern __shared__ float sh[];
    float* shW = sh;                    // 128 * WPAD
    float* shX = sh + 128 * WPAD;       // EV * WPAD (reused as partials + msg staging)
    __shared__ int s_key[EV];
    __shared__ int s_t[EV];

    const int tid  = threadIdx.x;
    const int row  = tid & 127;
    const int half = tid >> 7;
    const int side = (blockIdx.x >= HALF) ? 1 : 0;
    const int bid  = side ? (blockIdx.x - HALF) : blockIdx.x;
    const float* W = side ? Wd : Ws;
    const float bias = (side ? bd : bs)[row];

    // load W into smem with padded rows (256 threads)
    for (int idx = tid; idx < 128 * KMSG; idx += 256)
        shW[(idx / KMSG) * WPAD + (idx % KMSG)] = W[idx];
    __syncthreads();

    for (int e0 = bid * EV; e0 < EE; e0 += HALF * EV) {
        // ---- keys / timestamps ----
        if (tid < EV) {
            int e = e0 + tid;
            if (e < EE) {
                s_key[tid] = side ? dst[e] : src[e];
                s_t[tid]   = tt[e];
            }
        }
        // ---- gather x = [mem_a, mem_b, raw] : 8 events x 96 float4 ----
        for (int idx = tid; idx < EV * 96; idx += 256) {
            int ev = idx / 96, p = idx - ev * 96;
            int e = e0 + ev;
            if (e < EE) {
                int vs = src[e], vd = dst[e];
                int a = side ? vd : vs;
                int b = side ? vs : vd;
                float4 v;
                if (p < 32)       v = ((const float4*)(mem + (size_t)a * DD))[p];
                else if (p < 64)  v = ((const float4*)(mem + (size_t)b * DD))[p - 32];
                else              v = ((const float4*)(raw + (size_t)e * RR))[p - 64];
                ((float4*)(shX + ev * WPAD))[p] = v;
            }
        }
        // ---- time encoding: one element per thread (8 ev x 32) ----
        {
            int ev = tid >> 5, j = tid & 31;
            int e = e0 + ev;
            if (e < EE) {
                int a = side ? dst[e] : src[e];
                // replicate reference fp32 arg exactly, then reduce in double
                float trel = __fsub_rn((float)tt[e], (float)lu[a]);
                float arg  = __fadd_rn(__fmul_rn(trel, tw[j]), tb[j]);
                double d  = (double)arg;
                double kq = rint(d * 0.15915494309189535);
                double rd = d - kq * 6.283185307179586;
                shX[ev * WPAD + 384 + j] = cosf((float)rd);
            }
        }
        __syncthreads();

        // ---- split-K GEMV ----
        float acc[EV];
        #pragma unroll
        for (int ev = 0; ev < EV; ev++) acc[ev] = 0.f;
        const float4* wr = (const float4*)(shW + row * WPAD) + half * KH;
        const int xoff = half * KH;
        #pragma unroll 4
        for (int k = 0; k < KH; k++) {
            float4 w = wr[k];
            #pragma unroll
            for (int ev = 0; ev < EV; ev++) {
                float4 xv = ((const float4*)(shX + ev * WPAD))[xoff + k];
                acc[ev] = fmaf(w.x, xv.x, acc[ev]);
                acc[ev] = fmaf(w.y, xv.y, acc[ev]);
                acc[ev] = fmaf(w.z, xv.z, acc[ev]);
                acc[ev] = fmaf(w.w, xv.w, acc[ev]);
            }
        }
        __syncthreads();

        // ---- combine K halves + relu, staged in shX (reused) ----
        float* shM = shX;   // 8 x 128, overwrites gathered X (no longer needed)
        if (half) {
            #pragma unroll
            for (int ev = 0; ev < EV; ev++) shM[ev * DD + row] = acc[ev];
        }
        __syncthreads();
        if (!half) {
            #pragma unroll
            for (int ev = 0; ev < EV; ev++)
                shM[ev * DD + row] = fmaxf(acc[ev] + shM[ev * DD + row] + bias, 0.f);
        }
        __syncthreads();

        // ---- scatter float4 atomics (one per thread) ----
        if (tid < EV * 32) {
            int ev = tid >> 5, j = tid & 31;
            if (e0 + ev < EE) {
                float4 v = *(const float4*)(shM + ev * DD + j * 4);
                atomicAdd((float4*)&g_sums[(size_t)s_key[ev] * DD + j * 4], v);
            }
        }
        if (tid < EV && (e0 + tid) < EE) {
            atomicAdd(&g_cnt[s_key[tid]], 1.0f);
            atomicMax(&g_tmax[s_key[tid]], s_t[tid]);
        }
        __syncthreads();
    }
}

// ============================================================
// gi = aggr @ W_ih^T + b_ih   (aggr computed on the fly from sums/cnt)
// ============================================================
__global__ void __launch_bounds__(GOUT, 1) k_gi(
    const float* __restrict__ Wih, const float* __restrict__ bih)
{
    extern __shared__ float sh[];
    float* shW = sh;                       // GOUT * GP
    float* shX = sh + GOUT * GP;           // NODES_GI * GK
    const int tid = threadIdx.x;

    for (int idx = tid; idx < GOUT * GK; idx += GOUT)
        shW[(idx / GK) * GP + (idx % GK)] = Wih[idx];
    const float bias = bih[tid];
    __syncthreads();

    for (int n0 = blockIdx.x * NODES_GI; n0 < NN; n0 += gridDim.x * NODES_GI) {
        for (int i = tid; i < NODES_GI * GK; i += GOUT) {
            int node = i >> 7, d = i & 127;
            int n = n0 + node;
            float v = 0.f;
            if (n < NN) {
                float c = g_cnt[n];
                v = g_sums[(size_t)n * DD + d] / fmaxf(c, 1.0f);
            }
            shX[node * GK + d] = v;
        }
        __syncthreads();

        float acc[NODES_GI];
        #pragma unroll
        for (int j = 0; j < NODES_GI; j++) acc[j] = 0.f;
        const float4* wr = (const float4*)(shW + tid * GP);
        const float4* xp = (const float4*)shX;
        #pragma unroll 4
        for (int k = 0; k < GK / 4; k++) {
            float4 w = wr[k];
            #pragma unroll
            for (int j = 0; j < NODES_GI; j++) {
                float4 xv = xp[j * (GK / 4) + k];
                acc[j] = fmaf(w.x, xv.x, acc[j]);
                acc[j] = fmaf(w.y, xv.y, acc[j]);
                acc[j] = fmaf(w.z, xv.z, acc[j]);
                acc[j] = fmaf(w.w, xv.w, acc[j]);
            }
        }
        #pragma unroll
        for (int j = 0; j < NODES_GI; j++) {
            int n = n0 + j;
            if (n < NN) g_gi[(size_t)n * GOUT + tid] = acc[j] + bias;
        }
        __syncthreads();
    }
}

// ============================================================
// gh = memory @ W_hh^T + b_hh, then GRU combine -> new_memory
// ============================================================
__global__ void __launch_bounds__(GOUT, 1) k_out(
    const float* __restrict__ mem, const float* __restrict__ Whh,
    const float* __restrict__ bhh, float* __restrict__ out)
{
    extern __shared__ float sh[];
    float* shW = sh;                             // GOUT * GP
    float* shM = sh + GOUT * GP;                 // NODES_OUT * GK
    float* shG = shM + NODES_OUT * GK;           // NODES_OUT * GOUT
    const int tid = threadIdx.x;

    for (int idx = tid; idx < GOUT * GK; idx += GOUT)
        shW[(idx / GK) * GP + (idx % GK)] = Whh[idx];
    const float bias = bhh[tid];
    __syncthreads();

    for (int n0 = blockIdx.x * NODES_OUT; n0 < NN; n0 += gridDim.x * NODES_OUT) {
        for (int i = tid; i < NODES_OUT * GK; i += GOUT) {
            int node = i >> 7, d = i & 127;
            int n = n0 + node;
            shM[node * GK + d] = (n < NN) ? mem[(size_t)n * GK + d] : 0.f;
        }
        __syncthreads();

        float acc[NODES_OUT];
        #pragma unroll
        for (int j = 0; j < NODES_OUT; j++) acc[j] = 0.f;
        const float4* wr = (const float4*)(shW + tid * GP);
        const float4* xp = (const float4*)shM;
        #pragma unroll
        for (int k = 0; k < GK / 4; k++) {
            float4 w = wr[k];
            #pragma unroll
            for (int j = 0; j < NODES_OUT; j++) {
                float4 xv = xp[j * (GK / 4) + k];
                acc[j] = fmaf(w.x, xv.x, acc[j]);
                acc[j] = fmaf(w.y, xv.y, acc[j]);
                acc[j] = fmaf(w.z, xv.z, acc[j]);
                acc[j] = fmaf(w.w, xv.w, acc[j]);
            }
        }
        #pragma unroll
        for (int j = 0; j < NODES_OUT; j++)
            shG[j * GOUT + tid] = acc[j] + bias;
        __syncthreads();

        for (int i = tid; i < NODES_OUT * GK; i += GOUT) {
            int node = i >> 7, d = i & 127;
            int n = n0 + node;
            if (n < NN) {
                size_t gb = (size_t)n * GOUT;
                float ir = g_gi[gb + d], iz = g_gi[gb + 128 + d], inn = g_gi[gb + 256 + d];
                float hr = shG[node * GOUT + d];
                float hz = shG[node * GOUT + 128 + d];
                float hn = shG[node * GOUT + 256 + d];
                float rg = 1.f / (1.f + expf(-(ir + hr)));
                float zg = 1.f / (1.f + expf(-(iz + hz)));
                float ng = tanhf(inn + rg * hn);
                out[(size_t)n * GK + d] = (1.f - zg) * ng + zg * shM[node * GK + d];
            }
        }
        __syncthreads();
    }
}

// ============================================================
// new_last_update (reference: where(cnt>0, segment_max(t), 0))
// ============================================================
__global__ void k_lu(float* __restrict__ out) {
    int i = blockIdx.x * blockDim.x + threadIdx.x;
    if (i < NN)
        out[(size_t)NN * DD + i] = (g_cnt[i] > 0.f) ? (float)g_tmax[i] : 0.f;
}

// ============================================================
extern "C" void kernel_launch(void* const* d_in, const int* in_sizes, int n_in,
                              void* d_out, int out_size)
{
    const float* mem = (const float*)d_in[0];
    const float* raw = (const float*)d_in[1];
    const float* tw  = (const float*)d_in[2];
    const float* tb  = (const float*)d_in[3];
    const float* Ws  = (const float*)d_in[4];
    const float* bs  = (const float*)d_in[5];
    const float* Wd  = (const float*)d_in[6];
    const float* bd  = (const float*)d_in[7];
    const float* Wih = (const float*)d_in[8];
    const float* Whh = (const float*)d_in[9];
    const float* bih = (const float*)d_in[10];
    const float* bhh = (const float*)d_in[11];
    const int* src = (const int*)d_in[12];
    const int* dst = (const int*)d_in[13];
    const int* tt  = (const int*)d_in[14];
    const int* lu  = (const int*)d_in[15];
    float* out = (float*)d_out;

    size_t smem_msg = (size_t)(128 * WPAD + EV * WPAD) * sizeof(float);               // 228480
    size_t smem_gi  = (size_t)(GOUT * GP + NODES_GI * GK) * sizeof(float);            // 210944
    size_t smem_out = (size_t)(GOUT * GP + NODES_OUT * GK + NODES_OUT * GOUT) * sizeof(float); // 219136

    cudaFuncSetAttribute(k_msg, cudaFuncAttributeMaxDynamicSharedMemorySize, (int)smem_msg);
    cudaFuncSetAttribute(k_gi,  cudaFuncAttributeMaxDynamicSharedMemorySize, (int)smem_gi);
    cudaFuncSetAttribute(k_out, cudaFuncAttributeMaxDynamicSharedMemorySize, (int)smem_out);

    k_init<<<2048, 256>>>();
    k_msg<<<2 * HALF, 256, smem_msg>>>(mem, raw, tw, tb, Ws, bs, Wd, bd, src, dst, tt, lu);
    k_gi <<<HALF, GOUT, smem_gi>>>(Wih, bih);
    k_out<<<HALF, GOUT, smem_out>>>(mem, Whh, bhh, out);
    if (out_size >= NN * DD + NN)
        k_lu<<<(NN + 255) / 256, 256>>>(out);
}

// round 3
// speedup vs baseline: 1.9026x; 1.2289x over previous
#include <cuda_runtime.h>
#include <math.h>

#define NN 131072
#define EE 262144
#define DD 128
#define RR 128
#define TT 32
#define KMSG 416      // 2D + R + T
#define WPAD 420      // smem row stride for W_msg (4l mod 32 pattern -> conflict-free LDS.128)
#define EV 8          // events per W pass
#define HALF 148      // blocks per message side
#define KQ 26         // float4s per K quarter (104 total)
#define GK 128
#define GP 132        // row stride for GRU W in smem (conflict-free)
#define GOUT 384

// -------- device scratch (no allocation allowed) --------
__device__ float g_sums[(size_t)NN * DD];   // 64 MB
__device__ float g_cnt[NN];
__device__ int   g_tmax[NN];
__device__ float g_gi[(size_t)NN * GOUT];   // 192 MB

// ============================================================
__global__ void k_init() {
    size_t i = (size_t)blockIdx.x * blockDim.x + threadIdx.x;
    size_t stride = (size_t)gridDim.x * blockDim.x;
    float4* s4 = (float4*)g_sums;
    size_t n4 = (size_t)NN * DD / 4;
    for (size_t idx = i; idx < n4; idx += stride) s4[idx] = make_float4(0.f, 0.f, 0.f, 0.f);
    for (size_t idx = i; idx < NN; idx += stride) { g_cnt[idx] = 0.f; g_tmax[idx] = 0; }
}

// ============================================================
// message MLPs + scatter. 512 threads, 4-way split-K, register prefetch.
//   row = tid & 127, half = tid >> 7 (K quarter)
// blockIdx.x < HALF : source-side (key=src, W_msg_s); else dest-side.
// ============================================================
__global__ void __launch_bounds__(512, 1) k_msg(
    const float* __restrict__ mem, const float* __restrict__ raw,
    const float* __restrict__ tw,  const float* __restrict__ tb,
    const float* __restrict__ Ws,  const float* __restrict__ bs,
    const float* __restrict__ Wd,  const float* __restrict__ bd,
    const int* __restrict__ src, const int* __restrict__ dst,
    const int* __restrict__ tt,  const int* __restrict__ lu)
{
    extern __shared__ float sh[];
    float* shW = sh;                    // 128 * WPAD
    float* shX = sh + 128 * WPAD;       // EV * WPAD (reused: partials + msg staging)
    __shared__ int s_key[EV];
    __shared__ int s_t[EV];

    const int tid  = threadIdx.x;
    const int row  = tid & 127;
    const int half = tid >> 7;          // 0..3
    const int side = (blockIdx.x >= HALF) ? 1 : 0;
    const int bid  = side ? (blockIdx.x - HALF) : blockIdx.x;
    const float* W = side ? Wd : Ws;
    const float bias = (side ? bd : bs)[row];
    const int STRIDE = HALF * EV;

    // gather mapping constants (idx = tid and idx = tid+512 for tid<256)
    const int ev0 = tid / 96,          p0 = tid - ev0 * 96;
    const int ev1 = (tid + 512) / 96,  p1 = (tid + 512) - ev1 * 96;
    const bool has2 = (tid < 256);
    // time-enc lane mapping (tid < 256)
    const int evt = tid >> 5, jt = tid & 31;
    const float twj = tw[jt & 31];
    const float tbj = tb[jt & 31];

    // load W into smem with padded rows
    for (int idx = tid; idx < 128 * KMSG; idx += 512)
        shW[(idx / KMSG) * WPAD + (idx % KMSG)] = W[idx];

    // ---- prefetch helper (expanded inline) ----
    float4 pf_a = make_float4(0.f,0.f,0.f,0.f), pf_b = make_float4(0.f,0.f,0.f,0.f);
    float  pf_tf = 0.f, pf_luf = 0.f;
    int    pf_key = 0, pf_ts = 0;

#define PREFETCH(E0) do {                                                     \
    { int e = (E0) + ev0; int vs = src[e], vd = dst[e];                       \
      int a = side ? vd : vs, b = side ? vs : vd;                             \
      if (p0 < 32)      pf_a = ((const float4*)(mem + (size_t)a * DD))[p0];   \
      else if (p0 < 64) pf_a = ((const float4*)(mem + (size_t)b * DD))[p0-32];\
      else              pf_a = ((const float4*)(raw + (size_t)e * RR))[p0-64];}\
    if (has2) {                                                               \
      int e = (E0) + ev1; int vs = src[e], vd = dst[e];                       \
      int a = side ? vd : vs, b = side ? vs : vd;                             \
      if (p1 < 32)      pf_b = ((const float4*)(mem + (size_t)a * DD))[p1];   \
      else if (p1 < 64) pf_b = ((const float4*)(mem + (size_t)b * DD))[p1-32];\
      else              pf_b = ((const float4*)(raw + (size_t)e * RR))[p1-64];}\
    if (tid < 256) {                                                          \
      int e = (E0) + evt;                                                     \
      int a = side ? dst[e] : src[e];                                         \
      pf_tf = (float)tt[e]; pf_luf = (float)lu[a]; }                          \
    if (tid < EV) {                                                           \
      int e = (E0) + tid;                                                     \
      pf_key = side ? dst[e] : src[e]; pf_ts = tt[e]; }                       \
} while (0)

    PREFETCH(bid * EV);
    __syncthreads();   // W ready (prefetch overlapped)

    for (int e0 = bid * EV; e0 < EE; e0 += STRIDE) {
        // ---- store prefetched pass into shX ----
        ((float4*)(shX + ev0 * WPAD))[p0] = pf_a;
        if (has2) ((float4*)(shX + ev1 * WPAD))[p1] = pf_b;
        if (tid < 256) {
            // replicate reference fp32 arg exactly, then reduce in double
            float trel = __fsub_rn(pf_tf, pf_luf);
            float arg  = __fadd_rn(__fmul_rn(trel, twj), tbj);
            double d  = (double)arg;
            double kq = rint(d * 0.15915494309189535);
            double rd = d - kq * 6.283185307179586;
            shX[evt * WPAD + 384 + jt] = cosf((float)rd);
        }
        if (tid < EV) { s_key[tid] = pf_key; s_t[tid] = pf_ts; }
        __syncthreads();   // X ready

        // ---- issue next pass prefetch (in flight during GEMV) ----
        int e0n = e0 + STRIDE;
        if (e0n < EE) PREFETCH(e0n);

        // ---- split-K GEMV ----
        float acc[EV];
        #pragma unroll
        for (int ev = 0; ev < EV; ev++) acc[ev] = 0.f;
        const float4* wr = (const float4*)(shW + row * WPAD) + half * KQ;
        const int xoff = half * KQ;
        #pragma unroll
        for (int k = 0; k < KQ; k++) {
            float4 w = wr[k];
            #pragma unroll
            for (int ev = 0; ev < EV; ev++) {
                float4 xv = ((const float4*)(shX + ev * WPAD))[xoff + k];
                acc[ev] = fmaf(w.x, xv.x, acc[ev]);
                acc[ev] = fmaf(w.y, xv.y, acc[ev]);
                acc[ev] = fmaf(w.z, xv.z, acc[ev]);
                acc[ev] = fmaf(w.w, xv.w, acc[ev]);
            }
        }
        __syncthreads();   // done reading shX

        // ---- combine quarters: halves 1..3 stage partials in shX (dead) ----
        if (half) {
            float* shP = shX + (half - 1) * (EV * DD);
            #pragma unroll
            for (int ev = 0; ev < EV; ev++) shP[ev * DD + row] = acc[ev];
        }
        __syncthreads();
        if (!half) {
            #pragma unroll
            for (int ev = 0; ev < EV; ev++) {
                float m = acc[ev] + shX[0 * EV * DD + ev * DD + row]
                                  + shX[1 * EV * DD + ev * DD + row]
                                  + shX[2 * EV * DD + ev * DD + row] + bias;
                shX[ev * DD + row] = fmaxf(m, 0.f);   // shM overlays partial 0
            }
        }
        __syncthreads();

        // ---- scatter float4 atomics ----
        if (tid < EV * 32) {
            int ev = tid >> 5, j = tid & 31;
            float4 v = *(const float4*)(shX + ev * DD + j * 4);
            atomicAdd((float4*)&g_sums[(size_t)s_key[ev] * DD + j * 4], v);
        }
        if (tid < EV) {
            atomicAdd(&g_cnt[s_key[tid]], 1.0f);
            atomicMax(&g_tmax[s_key[tid]], s_t[tid]);
        }
        __syncthreads();   // shX free for next pass's stores
    }
#undef PREFETCH
}

// ============================================================
// gi = aggr @ W_ih^T + b_ih. 768 threads, 2-way split-K, 8 nodes/tile.
// ============================================================
__global__ void __launch_bounds__(768, 1) k_gi(
    const float* __restrict__ Wih, const float* __restrict__ bih)
{
    extern __shared__ float sh[];
    float* shW = sh;                       // GOUT * GP
    float* shX = sh + GOUT * GP;           // 8 * GK   = 1024
    float* shP = shX + 8 * GK;             // 8 * GOUT = 3072
    const int tid = threadIdx.x;
    const int half = (tid >= GOUT) ? 1 : 0;
    const int row  = tid - half * GOUT;

    for (int idx = tid; idx < GOUT * GK; idx += 768)
        shW[(idx / GK) * GP + (idx % GK)] = Wih[idx];
    const float bias = bih[row];
    __syncthreads();

    for (int n0 = blockIdx.x * 8; n0 < NN; n0 += gridDim.x * 8) {
        for (int idx = tid; idx < 8 * GK; idx += 768) {
            int node = idx >> 7, d = idx & 127;
            int n = n0 + node;
            shX[idx] = g_sums[(size_t)n * DD + d] / fmaxf(g_cnt[n], 1.0f);
        }
        __syncthreads();

        float acc[8];
        #pragma unroll
        for (int j = 0; j < 8; j++) acc[j] = 0.f;
        const float4* wr = (const float4*)(shW + row * GP) + half * 16;
        const int xoff = half * 16;
        #pragma unroll
        for (int k = 0; k < 16; k++) {
            float4 w = wr[k];
            #pragma unroll
            for (int j = 0; j < 8; j++) {
                float4 xv = ((const float4*)(shX + j * GK))[xoff + k];
                acc[j] = fmaf(w.x, xv.x, acc[j]);
                acc[j] = fmaf(w.y, xv.y, acc[j]);
                acc[j] = fmaf(w.z, xv.z, acc[j]);
                acc[j] = fmaf(w.w, xv.w, acc[j]);
            }
        }
        if (half) {
            #pragma unroll
            for (int j = 0; j < 8; j++) shP[j * GOUT + row] = acc[j];
        }
        __syncthreads();
        if (!half) {
            #pragma unroll
            for (int j = 0; j < 8; j++)
                g_gi[(size_t)(n0 + j) * GOUT + row] = acc[j] + shP[j * GOUT + row] + bias;
        }
        __syncthreads();
    }
}

// ============================================================
// gh = memory @ W_hh^T + b_hh, then GRU combine -> new_memory.
// 768 threads, 2-way split-K, 8 nodes/tile.
// ============================================================
__global__ void __launch_bounds__(768, 1) k_out(
    const float* __restrict__ mem, const float* __restrict__ Whh,
    const float* __restrict__ bhh, float* __restrict__ out)
{
    extern __shared__ float sh[];
    float* shW = sh;                         // GOUT * GP
    float* shM = sh + GOUT * GP;             // 8 * GK   = 1024
    float* shG = shM + 8 * GK;               // 8 * GOUT = 3072
    const int tid = threadIdx.x;
    const int half = (tid >= GOUT) ? 1 : 0;
    const int row  = tid - half * GOUT;

    for (int idx = tid; idx < GOUT * GK; idx += 768)
        shW[(idx / GK) * GP + (idx % GK)] = Whh[idx];
    const float bias = bhh[row];
    __syncthreads();

    for (int n0 = blockIdx.x * 8; n0 < NN; n0 += gridDim.x * 8) {
        for (int idx = tid; idx < 8 * GK; idx += 768) {
            int node = idx >> 7, d = idx & 127;
            shM[idx] = mem[(size_t)(n0 + node) * GK + d];
        }
        __syncthreads();

        float acc[8];
        #pragma unroll
        for (int j = 0; j < 8; j++) acc[j] = 0.f;
        const float4* wr = (const float4*)(shW + row * GP) + half * 16;
        const int xoff = half * 16;
        #pragma unroll
        for (int k = 0; k < 16; k++) {
            float4 w = wr[k];
            #pragma unroll
            for (int j = 0; j < 8; j++) {
                float4 xv = ((const float4*)(shM + j * GK))[xoff + k];
                acc[j] = fmaf(w.x, xv.x, acc[j]);
                acc[j] = fmaf(w.y, xv.y, acc[j]);
                acc[j] = fmaf(w.z, xv.z, acc[j]);
                acc[j] = fmaf(w.w, xv.w, acc[j]);
            }
        }
        if (half) {
            #pragma unroll
            for (int j = 0; j < 8; j++) shG[j * GOUT + row] = acc[j];
        }
        __syncthreads();
        if (!half) {
            #pragma unroll
            for (int j = 0; j < 8; j++)
                shG[j * GOUT + row] += acc[j] + bias;
        }
        __syncthreads();

        for (int idx = tid; idx < 8 * GK; idx += 768) {
            int node = idx >> 7, d = idx & 127;
            int n = n0 + node;
            size_t gb = (size_t)n * GOUT;
            float ir = g_gi[gb + d], iz = g_gi[gb + 128 + d], inn = g_gi[gb + 256 + d];
            float hr = shG[node * GOUT + d];
            float hz = shG[node * GOUT + 128 + d];
            float hn = shG[node * GOUT + 256 + d];
            float rg = 1.f / (1.f + expf(-(ir + hr)));
            float zg = 1.f / (1.f + expf(-(iz + hz)));
            float ng = tanhf(inn + rg * hn);
            out[(size_t)n * GK + d] = (1.f - zg) * ng + zg * shM[idx];
        }
        __syncthreads();
    }
}

// ============================================================
__global__ void k_lu(float* __restrict__ out) {
    int i = blockIdx.x * blockDim.x + threadIdx.x;
    if (i < NN)
        out[(size_t)NN * DD + i] = (g_cnt[i] > 0.f) ? (float)g_tmax[i] : 0.f;
}

// ============================================================
extern "C" void kernel_launch(void* const* d_in, const int* in_sizes, int n_in,
                              void* d_out, int out_size)
{
    const float* mem = (const float*)d_in[0];
    const float* raw = (const float*)d_in[1];
    const float* tw  = (const float*)d_in[2];
    const float* tb  = (const float*)d_in[3];
    const float* Ws  = (const float*)d_in[4];
    const float* bs  = (const float*)d_in[5];
    const float* Wd  = (const float*)d_in[6];
    const float* bd  = (const float*)d_in[7];
    const float* Wih = (const float*)d_in[8];
    const float* Whh = (const float*)d_in[9];
    const float* bih = (const float*)d_in[10];
    const float* bhh = (const float*)d_in[11];
    const int* src = (const int*)d_in[12];
    const int* dst = (const int*)d_in[13];
    const int* tt  = (const int*)d_in[14];
    const int* lu  = (const int*)d_in[15];
    float* out = (float*)d_out;

    size_t smem_msg = (size_t)(128 * WPAD + EV * WPAD) * sizeof(float);         // 228480
    size_t smem_gru = (size_t)(GOUT * GP + 8 * GK + 8 * GOUT) * sizeof(float);  // 219136

    cudaFuncSetAttribute(k_msg, cudaFuncAttributeMaxDynamicSharedMemorySize, (int)smem_msg);
    cudaFuncSetAttribute(k_gi,  cudaFuncAttributeMaxDynamicSharedMemorySize, (int)smem_gru);
    cudaFuncSetAttribute(k_out, cudaFuncAttributeMaxDynamicSharedMemorySize, (int)smem_gru);

    k_init<<<2048, 256>>>();
    k_msg<<<2 * HALF, 512, smem_msg>>>(mem, raw, tw, tb, Ws, bs, Wd, bd, src, dst, tt, lu);
    k_gi <<<HALF, 768, smem_gru>>>(Wih, bih);
    k_out<<<HALF, 768, smem_gru>>>(mem, Whh, bhh, out);
    if (out_size >= NN * DD + NN)
        k_lu<<<(NN + 255) / 256, 256>>>(out);
}

// round 4
// speedup vs baseline: 2.6490x; 1.3923x over previous
#include <cuda_runtime.h>
#include <math.h>

#define NN 131072
#define EE 262144
#define DD 128
#define RR 128
#define KMSG 416
#define KH2 208        // K half for message GEMM
#define WP 212         // smem row stride (floats) for msg W/X; 212/4=53 f4 (odd -> conflict-free)
#define W4 53
#define EVT 64         // events per tile
#define SST 132        // staging stride
#define NB 148
#define GP 132         // GRU W row stride; 33 f4 (odd)
#define G4 33
#define GOUT 384
#define NT 32          // nodes per GRU tile

// -------- device scratch --------
__device__ float g_sums[(size_t)NN * DD];
__device__ float g_cnt[NN];
__device__ int   g_tmax[NN];
__device__ float g_pA[(size_t)2 * EE * DD];   // K-half 0 partials (268MB)
__device__ float g_pB[(size_t)2 * EE * DD];   // K-half 1 partials
__device__ float g_gi[(size_t)NN * GOUT];
__device__ float g_gh[(size_t)NN * GOUT];

// ============================================================
__global__ void k_init() {
    size_t i = (size_t)blockIdx.x * blockDim.x + threadIdx.x;
    size_t stride = (size_t)gridDim.x * blockDim.x;
    float4* s4 = (float4*)g_sums;
    for (size_t idx = i; idx < (size_t)NN * DD / 4; idx += stride)
        s4[idx] = make_float4(0.f, 0.f, 0.f, 0.f);
    for (size_t idx = i; idx < NN; idx += stride) { g_cnt[idx] = 0.f; g_tmax[idx] = 0; }
}

// ============================================================
// Message GEMM partials. grid = 4*NB: g = blk/NB -> side = g&1, kh = g>>1.
// Block: W-half (128 x 208) persistent, stream 64-event X tiles.
// 512 threads: rg = tid & 63 (rows rg, rg+64), eg = tid >> 6 (events eg*8..+8).
// Thread tile 2x8 -> per k-quad: 2 w.128 + 8 x.128 (broadcast) / 64 FFMA.
// ============================================================
__global__ void __launch_bounds__(512, 1) k_msgA(
    const float* __restrict__ mem, const float* __restrict__ raw,
    const float* __restrict__ tw,  const float* __restrict__ tb,
    const float* __restrict__ Ws,  const float* __restrict__ Wd,
    const int* __restrict__ src, const int* __restrict__ dst,
    const int* __restrict__ tt,  const int* __restrict__ lu)
{
    extern __shared__ float sh[];
    float* shW = sh;                 // 128 * WP
    float* shX = sh + 128 * WP;      // EVT * WP   (reused as staging 64*SST)
    float4* shW4 = (float4*)shW;
    float4* shX4 = (float4*)shX;

    const int tid  = threadIdx.x;
    const int g    = blockIdx.x / NB;
    const int bid  = blockIdx.x - g * NB;
    const int side = g & 1;
    const int kh   = g >> 1;
    const int rg   = tid & 63;
    const int eg   = tid >> 6;
    const float* W = side ? Wd : Ws;
    float* gp = kh ? g_pB : g_pA;

    // ---- load W half: rows 128, cols [kh*208, +208) -> shW stride WP ----
    for (int i4 = tid; i4 < 128 * 52; i4 += 512) {
        int row = i4 / 52, c4 = i4 - row * 52;
        shW4[row * W4 + c4] = ((const float4*)W)[row * 104 + kh * 52 + c4];
    }

    // ---- gather index precompute (fixed per thread) ----
    const int NC4 = kh ? 44 : 52;          // f4 gather cols (kh1 excludes tenc)
    const int NIDX = EVT * NC4;
    int evz[7], c4z[7];
    #pragma unroll
    for (int z = 0; z < 7; z++) {
        int idx = tid + z * 512;
        if (idx < NIDX) { evz[z] = idx / NC4; c4z[z] = idx - (idx / NC4) * NC4; }
        else evz[z] = -1;
    }
    const int jt = tid & 31;               // tenc lane
    const float twj = tw[jt], tbj = tb[jt];

    float4 pf[7];
    float pt[4], plu[4];

#define PREFETCH(E0) do {                                                      \
    _Pragma("unroll")                                                          \
    for (int z = 0; z < 7; z++) if (evz[z] >= 0) {                             \
        int e = (E0) + evz[z]; int c4 = c4z[z];                                \
        int vs = src[e], vd = dst[e];                                          \
        int a = side ? vd : vs, b = side ? vs : vd;                            \
        const float4* p; int f4;                                               \
        if (!kh) { if (c4 < 32) { p = (const float4*)(mem + (size_t)a * DD); f4 = c4; }          \
                   else         { p = (const float4*)(mem + (size_t)b * DD); f4 = c4 - 32; } }   \
        else     { if (c4 < 12) { p = (const float4*)(mem + (size_t)b * DD); f4 = 20 + c4; }     \
                   else         { p = (const float4*)(raw + (size_t)e * RR); f4 = c4 - 12; } }   \
        pf[z] = p[f4];                                                         \
    }                                                                          \
    if (kh) {                                                                  \
        _Pragma("unroll")                                                      \
        for (int z = 0; z < 4; z++) {                                          \
            int ev = (tid >> 5) + z * 16; int e = (E0) + ev;                   \
            int a = side ? dst[e] : src[e];                                    \
            pt[z] = (float)tt[e]; plu[z] = (float)lu[a];                       \
        }                                                                      \
    }                                                                          \
} while (0)

    const int STRIDE = NB * EVT;
    PREFETCH(bid * EVT);
    __syncthreads();   // W ready

    for (int e0 = bid * EVT; e0 < EE; e0 += STRIDE) {
        // ---- A: store prefetched X ----
        #pragma unroll
        for (int z = 0; z < 7; z++) if (evz[z] >= 0)
            shX4[evz[z] * W4 + c4z[z]] = pf[z];
        if (kh) {
            #pragma unroll
            for (int z = 0; z < 4; z++) {
                int ev = (tid >> 5) + z * 16;
                float arg = __fadd_rn(__fmul_rn(__fsub_rn(pt[z], plu[z]), twj), tbj);
                double d  = (double)arg;
                double kq = rint(d * 0.15915494309189535);
                double rd = d - kq * 6.283185307179586;
                shX[ev * WP + 176 + jt] = cosf((float)rd);
            }
        }
        __syncthreads();   // X ready

        int e0n = e0 + STRIDE;
        if (e0n < EE) PREFETCH(e0n);

        // ---- GEMV 2x8 ----
        float acc[2][8];
        #pragma unroll
        for (int r = 0; r < 2; r++)
            #pragma unroll
            for (int j = 0; j < 8; j++) acc[r][j] = 0.f;
        #pragma unroll 4
        for (int c4 = 0; c4 < 52; c4++) {
            float4 w0 = shW4[rg * W4 + c4];
            float4 w1 = shW4[(rg + 64) * W4 + c4];
            #pragma unroll
            for (int j = 0; j < 8; j++) {
                float4 xv = shX4[(eg * 8 + j) * W4 + c4];
                acc[0][j] = fmaf(w0.x, xv.x, acc[0][j]);
                acc[0][j] = fmaf(w0.y, xv.y, acc[0][j]);
                acc[0][j] = fmaf(w0.z, xv.z, acc[0][j]);
                acc[0][j] = fmaf(w0.w, xv.w, acc[0][j]);
                acc[1][j] = fmaf(w1.x, xv.x, acc[1][j]);
                acc[1][j] = fmaf(w1.y, xv.y, acc[1][j]);
                acc[1][j] = fmaf(w1.z, xv.z, acc[1][j]);
                acc[1][j] = fmaf(w1.w, xv.w, acc[1][j]);
            }
        }
        __syncthreads();   // done reading shX

        // ---- stage partials [ev][row] stride SST ----
        #pragma unroll
        for (int j = 0; j < 8; j++) {
            shX[(eg * 8 + j) * SST + rg]      = acc[0][j];
            shX[(eg * 8 + j) * SST + rg + 64] = acc[1][j];
        }
        __syncthreads();

        // ---- coalesced float4 write to global partials ----
        for (int idx = tid; idx < EVT * 32; idx += 512) {
            int ev = idx >> 5, q = idx & 31;
            float4 v = *(const float4*)(shX + ev * SST + q * 4);
            *(float4*)(gp + ((size_t)(side ? EE : 0) + e0 + ev) * DD + q * 4) = v;
        }
        __syncthreads();
    }
#undef PREFETCH
}

// ============================================================
// finalize: sum K-halves + bias, relu, scatter atomics. warp per item.
// ============================================================
__global__ void __launch_bounds__(256) k_fin(
    const float* __restrict__ bs, const float* __restrict__ bd,
    const int* __restrict__ src, const int* __restrict__ dst,
    const int* __restrict__ tt)
{
    const int lane = threadIdx.x & 31;
    const int warp = threadIdx.x >> 5;
    const int IT = 2 * EE;
    for (int item = blockIdx.x * 8 + warp; item < IT; item += gridDim.x * 8) {
        int side = (item >= EE) ? 1 : 0;
        int e = item - (side ? EE : 0);
        int key = side ? dst[e] : src[e];
        float4 a = ((const float4*)g_pA)[(size_t)item * 32 + lane];
        float4 b = ((const float4*)g_pB)[(size_t)item * 32 + lane];
        float4 bb = ((const float4*)(side ? bd : bs))[lane];
        float4 v;
        v.x = fmaxf(a.x + b.x + bb.x, 0.f);
        v.y = fmaxf(a.y + b.y + bb.y, 0.f);
        v.z = fmaxf(a.z + b.z + bb.z, 0.f);
        v.w = fmaxf(a.w + b.w + bb.w, 0.f);
        atomicAdd((float4*)&g_sums[(size_t)key * DD + lane * 4], v);
        if (lane == 0) {
            atomicAdd(&g_cnt[key], 1.0f);
            atomicMax(&g_tmax[key], tt[e]);
        }
    }
}

// ============================================================
// GRU GEMM: y[n][0:384] = X[n] @ W^T (+bias). mode: 0 -> X=xs row; 1 -> X=g_sums/cnt.
// 768 threads: rg = tid % 192 (rows rg, rg+192), eg = tid / 192 (nodes eg*8..+8).
// ============================================================
__global__ void __launch_bounds__(768, 1) k_gemm(
    const float* __restrict__ W, const float* __restrict__ bias,
    const float* __restrict__ xs, int mode, float* __restrict__ y)
{
    extern __shared__ float sh[];
    float* shW = sh;                  // GOUT * GP
    float* shX = sh + GOUT * GP;      // NT * GP
    float4* shW4 = (float4*)shW;
    float4* shX4 = (float4*)shX;
    const int tid = threadIdx.x;
    const int eg = tid / 192;
    const int rg = tid - eg * 192;

    for (int i4 = tid; i4 < GOUT * 32; i4 += 768) {
        int row = i4 >> 5, c4 = i4 & 31;
        shW4[row * G4 + c4] = ((const float4*)W)[row * 32 + c4];
    }
    const float b0 = bias[rg], b1 = bias[rg + 192];
    __syncthreads();

    for (int n0 = blockIdx.x * NT; n0 < NN; n0 += gridDim.x * NT) {
        for (int i4 = tid; i4 < NT * 32; i4 += 768) {
            int node = i4 >> 5, c4 = i4 & 31;
            int n = n0 + node;
            float4 v = ((const float4*)xs)[(size_t)n * 32 + c4];
            if (mode) {
                float inv = 1.0f / fmaxf(g_cnt[n], 1.0f);
                v.x *= inv; v.y *= inv; v.z *= inv; v.w *= inv;
            }
            shX4[node * G4 + c4] = v;
        }
        __syncthreads();

        float acc[2][8];
        #pragma unroll
        for (int r = 0; r < 2; r++)
            #pragma unroll
            for (int j = 0; j < 8; j++) acc[r][j] = 0.f;
        #pragma unroll 4
        for (int c4 = 0; c4 < 32; c4++) {
            float4 w0 = shW4[rg * G4 + c4];
            float4 w1 = shW4[(rg + 192) * G4 + c4];
            #pragma unroll
            for (int j = 0; j < 8; j++) {
                float4 xv = shX4[(eg * 8 + j) * G4 + c4];
                acc[0][j] = fmaf(w0.x, xv.x, acc[0][j]);
                acc[0][j] = fmaf(w0.y, xv.y, acc[0][j]);
                acc[0][j] = fmaf(w0.z, xv.z, acc[0][j]);
                acc[0][j] = fmaf(w0.w, xv.w, acc[0][j]);
                acc[1][j] = fmaf(w1.x, xv.x, acc[1][j]);
                acc[1][j] = fmaf(w1.y, xv.y, acc[1][j]);
                acc[1][j] = fmaf(w1.z, xv.z, acc[1][j]);
                acc[1][j] = fmaf(w1.w, xv.w, acc[1][j]);
            }
        }
        // coalesced scalar stores (lanes = consecutive rg)
        #pragma unroll
        for (int j = 0; j < 8; j++) {
            size_t base = (size_t)(n0 + eg * 8 + j) * GOUT;
            y[base + rg]       = acc[0][j] + b0;
            y[base + rg + 192] = acc[1][j] + b1;
        }
        __syncthreads();
    }
}

// ============================================================
// GRU combine (elementwise, float4)
// ============================================================
__global__ void k_comb(const float* __restrict__ mem, float* __restrict__ out) {
    size_t i = (size_t)blockIdx.x * blockDim.x + threadIdx.x;
    size_t stride = (size_t)gridDim.x * blockDim.x;
    for (size_t i4 = i; i4 < (size_t)NN * 32; i4 += stride) {
        size_t n = i4 >> 5; int q = (int)(i4 & 31);
        size_t gb = n * 96 + q;
        float4 ir = ((const float4*)g_gi)[gb];
        float4 iz = ((const float4*)g_gi)[gb + 32];
        float4 in_ = ((const float4*)g_gi)[gb + 64];
        float4 hr = ((const float4*)g_gh)[gb];
        float4 hz = ((const float4*)g_gh)[gb + 32];
        float4 hn = ((const float4*)g_gh)[gb + 64];
        float4 m = ((const float4*)mem)[i4];
        float4 o;
        {
            float rg = 1.f / (1.f + expf(-(ir.x + hr.x)));
            float zg = 1.f / (1.f + expf(-(iz.x + hz.x)));
            float ng = tanhf(in_.x + rg * hn.x);
            o.x = (1.f - zg) * ng + zg * m.x;
        }
        {
            float rg = 1.f / (1.f + expf(-(ir.y + hr.y)));
            float zg = 1.f / (1.f + expf(-(iz.y + hz.y)));
            float ng = tanhf(in_.y + rg * hn.y);
            o.y = (1.f - zg) * ng + zg * m.y;
        }
        {
            float rg = 1.f / (1.f + expf(-(ir.z + hr.z)));
            float zg = 1.f / (1.f + expf(-(iz.z + hz.z)));
            float ng = tanhf(in_.z + rg * hn.z);
            o.z = (1.f - zg) * ng + zg * m.z;
        }
        {
            float rg = 1.f / (1.f + expf(-(ir.w + hr.w)));
            float zg = 1.f / (1.f + expf(-(iz.w + hz.w)));
            float ng = tanhf(in_.w + rg * hn.w);
            o.w = (1.f - zg) * ng + zg * m.w;
        }
        ((float4*)out)[i4] = o;
    }
}

// ============================================================
__global__ void k_lu(float* __restrict__ out) {
    int i = blockIdx.x * blockDim.x + threadIdx.x;
    if (i < NN)
        out[(size_t)NN * DD + i] = (g_cnt[i] > 0.f) ? (float)g_tmax[i] : 0.f;
}

// ============================================================
extern "C" void kernel_launch(void* const* d_in, const int* in_sizes, int n_in,
                              void* d_out, int out_size)
{
    const float* mem = (const float*)d_in[0];
    const float* raw = (const float*)d_in[1];
    const float* tw  = (const float*)d_in[2];
    const float* tb  = (const float*)d_in[3];
    const float* Ws  = (const float*)d_in[4];
    const float* bs  = (const float*)d_in[5];
    const float* Wd  = (const float*)d_in[6];
    const float* bd  = (const float*)d_in[7];
    const float* Wih = (const float*)d_in[8];
    const float* Whh = (const float*)d_in[9];
    const float* bih = (const float*)d_in[10];
    const float* bhh = (const float*)d_in[11];
    const int* src = (const int*)d_in[12];
    const int* dst = (const int*)d_in[13];
    const int* tt  = (const int*)d_in[14];
    const int* lu  = (const int*)d_in[15];
    float* out = (float*)d_out;

    float* d_gi; cudaGetSymbolAddress((void**)&d_gi, g_gi);
    float* d_gh; cudaGetSymbolAddress((void**)&d_gh, g_gh);
    float* d_sums; cudaGetSymbolAddress((void**)&d_sums, g_sums);

    size_t smem_msg = (size_t)(128 * WP + EVT * WP) * sizeof(float);   // 162816
    size_t smem_gru = (size_t)(GOUT * GP + NT * GP) * sizeof(float);   // 219648

    cudaFuncSetAttribute(k_msgA, cudaFuncAttributeMaxDynamicSharedMemorySize, (int)smem_msg);
    cudaFuncSetAttribute(k_gemm, cudaFuncAttributeMaxDynamicSharedMemorySize, (int)smem_gru);

    k_init<<<2048, 256>>>();
    k_msgA<<<4 * NB, 512, smem_msg>>>(mem, raw, tw, tb, Ws, Wd, src, dst, tt, lu);
    k_fin<<<2048, 256>>>(bs, bd, src, dst, tt);
    k_gemm<<<NB, 768, smem_gru>>>(Wih, bih, d_sums, 1, d_gi);
    k_gemm<<<NB, 768, smem_gru>>>(Whh, bhh, mem, 0, d_gh);
    k_comb<<<2048, 256>>>(mem, out);
    if (out_size >= NN * DD + NN)
        k_lu<<<(NN + 255) / 256, 256>>>(out);
}

// round 6
// speedup vs baseline: 3.4283x; 1.2942x over previous
#include <cuda_runtime.h>
#include <cuda_bf16.h>
#include <math.h>
#include <stdint.h>

#define NN 131072
#define EE 262144
#define DD 128
#define RR 128
#define NB 148
#define GP 132         // GRU W row stride; 33 f4 (odd -> conflict-free)
#define G4 33
#define GOUT 384
#define NT 32          // nodes per GRU tile

#define XW 232                             // X row stride in words (mod 32 == 8)
#define XROW (XW * 4)                      // 928 bytes
#define WLW 212                            // Wlo row stride in words (bank-spread)
#define OFF_WLO 0
#define OFF_XHI (128 * WLW * 4)            // 108544
#define OFF_XLO (OFF_XHI + 64 * XROW)      // 167936
#define SMEM_MSG (OFF_XLO + 64 * XROW)     // 227328

// -------- device scratch --------
__device__ float g_sums[(size_t)NN * DD];
__device__ float g_cnt[NN];
__device__ int   g_tmax[NN];
__device__ float g_gi[(size_t)NN * GOUT];
__device__ float g_gh[(size_t)NN * GOUT];

// ================= helpers =================
__device__ __forceinline__ void mma16816(float& c0, float& c1, float& c2, float& c3,
                                         uint32_t a0, uint32_t a1, uint32_t a2, uint32_t a3,
                                         uint32_t b0, uint32_t b1) {
    asm volatile("mma.sync.aligned.m16n8k16.row.col.f32.bf16.bf16.f32 "
        "{%0,%1,%2,%3}, {%4,%5,%6,%7}, {%8,%9}, {%0,%1,%2,%3};"
        : "+f"(c0), "+f"(c1), "+f"(c2), "+f"(c3)
        : "r"(a0), "r"(a1), "r"(a2), "r"(a3), "r"(b0), "r"(b1));
}
__device__ __forceinline__ uint32_t bfhi(float2 p) {
    __nv_bfloat162 h = __floats2bfloat162_rn(p.x, p.y);
    return *reinterpret_cast<uint32_t*>(&h);
}
__device__ __forceinline__ void bfsplit(float x, float y, uint32_t& hi, uint32_t& lo) {
    __nv_bfloat162 h = __floats2bfloat162_rn(x, y);
    float rx = x - __bfloat162float(h.x);
    float ry = y - __bfloat162float(h.y);
    __nv_bfloat162 l = __floats2bfloat162_rn(rx, ry);
    hi = *reinterpret_cast<uint32_t*>(&h);
    lo = *reinterpret_cast<uint32_t*>(&l);
}

// ============================================================
__global__ void k_init() {
    size_t i = (size_t)blockIdx.x * blockDim.x + threadIdx.x;
    size_t stride = (size_t)gridDim.x * blockDim.x;
    float4* s4 = (float4*)g_sums;
    for (size_t idx = i; idx < (size_t)NN * DD / 4; idx += stride)
        s4[idx] = make_float4(0.f, 0.f, 0.f, 0.f);
    for (size_t idx = i; idx < NN; idx += stride) { g_cnt[idx] = 0.f; g_tmax[idx] = 0; }
}

// ============================================================
// Message MLP via mma.sync bf16 3-term fp32 emulation + fused scatter.
// grid = 2*NB (side = blockIdx.x >= NB). 256 threads = 8 warps.
// Warp w owns output rows [w*16, w*16+16), full K = 416.
//   Whi: A-fragments in registers (26 ksteps x 4 regs).
//   Wlo: smem (natural word layout, stride WLW).
//   X: 64-event tiles, hi/lo bf16 in smem, permuted word layout so a B
//      fragment (b0,b1) is one aligned LDS.64.
// ============================================================
__global__ void __launch_bounds__(256, 1) k_msgT(
    const float* __restrict__ mem, const float* __restrict__ raw,
    const float* __restrict__ tw,  const float* __restrict__ tb,
    const float* __restrict__ Ws,  const float* __restrict__ bs,
    const float* __restrict__ Wd,  const float* __restrict__ bd,
    const int* __restrict__ src, const int* __restrict__ dst,
    const int* __restrict__ tt,  const int* __restrict__ lu)
{
    extern __shared__ char smem[];
    uint32_t* wlo = (uint32_t*)(smem + OFF_WLO);
    uint32_t* xhi = (uint32_t*)(smem + OFF_XHI);
    uint32_t* xlo = (uint32_t*)(smem + OFF_XLO);
    float* stage  = (float*)(smem + OFF_XLO);   // overlays xlo after sweeps

    const int tid  = threadIdx.x;
    const int wid  = tid >> 5;
    const int lane = tid & 31;
    const int g    = lane >> 2;
    const int tig  = lane & 3;
    const int side = (blockIdx.x >= NB);
    const int bid  = side ? blockIdx.x - NB : blockIdx.x;
    const float* W    = side ? Wd : Ws;
    const float* bias = side ? bd : bs;
    const int r0 = wid * 16;

    // ---- Wlo -> smem (natural layout: word p = k/2 at row*WLW + p) ----
    for (int idx = tid; idx < 128 * 104; idx += 256) {
        int r = idx / 104, c4 = idx - (idx / 104) * 104;
        float4 v = ((const float4*)W)[idx];
        uint32_t h0, l0, h1, l1;
        bfsplit(v.x, v.y, h0, l0);
        bfsplit(v.z, v.w, h1, l1);
        *(uint2*)((char*)smem + OFF_WLO + (size_t)r * (WLW * 4) + c4 * 8) = make_uint2(l0, l1);
    }

    // ---- Whi A-fragments in registers ----
    uint32_t whi[26][4];
    {
        const float* w0 = W + (size_t)(r0 + g) * 416 + 2 * tig;
        const float* w8 = w0 + 8 * 416;
        #pragma unroll
        for (int kk = 0; kk < 26; kk++) {
            whi[kk][0] = bfhi(*(const float2*)(w0 + kk * 16));
            whi[kk][1] = bfhi(*(const float2*)(w8 + kk * 16));
            whi[kk][2] = bfhi(*(const float2*)(w0 + kk * 16 + 8));
            whi[kk][3] = bfhi(*(const float2*)(w8 + kk * 16 + 8));
        }
    }
    const float b0r = bias[r0 + g], b1r = bias[r0 + g + 8];
    const float twj = tw[lane], tbj = tb[lane];

    for (int e0 = bid * 64; e0 < EE; e0 += NB * 64) {
        // ---- gather + split X (cols 0..383: mem_a | mem_b | raw) ----
        for (int idx = tid; idx < 64 * 96; idx += 256) {
            int ev = idx / 96, c4 = idx - (idx / 96) * 96;
            int e = e0 + ev;
            int vs = src[e], vd = dst[e];
            int a = side ? vd : vs, b = side ? vs : vd;
            const float4* p; int f4;
            if (c4 < 32)      { p = (const float4*)(mem + (size_t)a * DD); f4 = c4; }
            else if (c4 < 64) { p = (const float4*)(mem + (size_t)b * DD); f4 = c4 - 32; }
            else              { p = (const float4*)(raw + (size_t)e * RR); f4 = c4 - 64; }
            float4 v = p[f4];
            uint32_t h0, l0, h1, l1;
            bfsplit(v.x, v.y, h0, l0);
            bfsplit(v.z, v.w, h1, l1);
            int q = c4 & 3;
            int w = (c4 >> 2) * 8 + (q >> 1) + (q & 1) * 4;   // permuted slot
            uint32_t* xh = xhi + ev * XW + w;
            uint32_t* xl = xlo + ev * XW + w;
            xh[0] = h0; xh[2] = h1;
            xl[0] = l0; xl[2] = l1;
        }
        // ---- time encoding (cols 384..415), exact fp32 arg + double reduce ----
        #pragma unroll
        for (int z = 0; z < 8; z++) {
            int ev = wid + z * 8;
            int e = e0 + ev;
            int a = side ? dst[e] : src[e];
            float trel = __fsub_rn((float)tt[e], (float)lu[a]);
            float arg  = __fadd_rn(__fmul_rn(trel, twj), tbj);
            double d  = (double)arg;
            double kq = rint(d * 0.15915494309189535);
            double rd = d - kq * 6.283185307179586;
            float c = cosf((float)rd);
            __nv_bfloat16 h = __float2bfloat16(c);
            __nv_bfloat16 l = __float2bfloat16(c - __bfloat162float(h));
            int k  = 384 + lane;
            int p  = k >> 1;
            int pi = p & 7, kk = p >> 3;
            int w  = kk * 8 + ((pi < 4) ? 2 * pi : 2 * (pi - 4) + 1);
            int byo = ev * XROW + w * 4 + (k & 1) * 2;
            *(__nv_bfloat16*)((char*)smem + OFF_XHI + byo) = h;
            *(__nv_bfloat16*)((char*)smem + OFF_XLO + byo) = l;
        }
        __syncthreads();

        // ---- MMA sweeps ----
        float acc[8][4];
        #pragma unroll
        for (int et = 0; et < 8; et++)
            acc[et][0] = acc[et][1] = acc[et][2] = acc[et][3] = 0.f;

        // sweep 1: B = Xhi; A = Whi (regs) and Wlo (smem) — fused B loads
        #pragma unroll
        for (int kk = 0; kk < 26; kk++) {
            uint32_t a0 = wlo[(r0 + g) * WLW     + kk * 8 + tig];
            uint32_t a1 = wlo[(r0 + g + 8) * WLW + kk * 8 + tig];
            uint32_t a2 = wlo[(r0 + g) * WLW     + kk * 8 + tig + 4];
            uint32_t a3 = wlo[(r0 + g + 8) * WLW + kk * 8 + tig + 4];
            #pragma unroll
            for (int et = 0; et < 8; et++) {
                uint2 b = *(const uint2*)(xhi + (et * 8 + g) * XW + kk * 8 + 2 * tig);
                mma16816(acc[et][0], acc[et][1], acc[et][2], acc[et][3],
                         whi[kk][0], whi[kk][1], whi[kk][2], whi[kk][3], b.x, b.y);
                mma16816(acc[et][0], acc[et][1], acc[et][2], acc[et][3],
                         a0, a1, a2, a3, b.x, b.y);
            }
        }
        // sweep 2: B = Xlo; A = Whi
        #pragma unroll
        for (int kk = 0; kk < 26; kk++) {
            #pragma unroll
            for (int et = 0; et < 8; et++) {
                uint2 b = *(const uint2*)(xlo + (et * 8 + g) * XW + kk * 8 + 2 * tig);
                mma16816(acc[et][0], acc[et][1], acc[et][2], acc[et][3],
                         whi[kk][0], whi[kk][1], whi[kk][2], whi[kk][3], b.x, b.y);
            }
        }
        __syncthreads();   // all Xlo reads done -> stage may overlay

        // ---- stage relu(msg + bias), layout [ev][row] stride 132 ----
        #pragma unroll
        for (int et = 0; et < 8; et++) {
            int evl = et * 8 + 2 * tig;
            stage[evl * 132 + r0 + g]           = fmaxf(acc[et][0] + b0r, 0.f);
            stage[(evl + 1) * 132 + r0 + g]     = fmaxf(acc[et][1] + b0r, 0.f);
            stage[evl * 132 + r0 + g + 8]       = fmaxf(acc[et][2] + b1r, 0.f);
            stage[(evl + 1) * 132 + r0 + g + 8] = fmaxf(acc[et][3] + b1r, 0.f);
        }
        __syncthreads();

        // ---- scatter float4 atomics ----
        for (int idx = tid; idx < 64 * 32; idx += 256) {
            int ev = idx >> 5, q = idx & 31;
            int e = e0 + ev;
            int key = side ? dst[e] : src[e];
            float4 v = *(const float4*)(stage + ev * 132 + q * 4);
            atomicAdd((float4*)&g_sums[(size_t)key * DD + q * 4], v);
        }
        if (tid < 64) {
            int e = e0 + tid;
            int key = side ? dst[e] : src[e];
            atomicAdd(&g_cnt[key], 1.0f);
            atomicMax(&g_tmax[key], tt[e]);
        }
        __syncthreads();   // stage (xlo region) free before next gather
    }
}

// ============================================================
// GRU GEMM (FFMA, round-4 proven version)
// ============================================================
__global__ void __launch_bounds__(768, 1) k_gemm(
    const float* __restrict__ W, const float* __restrict__ bias,
    const float* __restrict__ xs, int mode, float* __restrict__ y)
{
    extern __shared__ float sh[];
    float* shW = sh;
    float* shX = sh + GOUT * GP;
    float4* shW4 = (float4*)shW;
    float4* shX4 = (float4*)shX;
    const int tid = threadIdx.x;
    const int eg = tid / 192;
    const int rg = tid - eg * 192;

    for (int i4 = tid; i4 < GOUT * 32; i4 += 768) {
        int row = i4 >> 5, c4 = i4 & 31;
        shW4[row * G4 + c4] = ((const float4*)W)[row * 32 + c4];
    }
    const float b0 = bias[rg], b1 = bias[rg + 192];
    __syncthreads();

    for (int n0 = blockIdx.x * NT; n0 < NN; n0 += gridDim.x * NT) {
        for (int i4 = tid; i4 < NT * 32; i4 += 768) {
            int node = i4 >> 5, c4 = i4 & 31;
            int n = n0 + node;
            float4 v = ((const float4*)xs)[(size_t)n * 32 + c4];
            if (mode) {
                float inv = 1.0f / fmaxf(g_cnt[n], 1.0f);
                v.x *= inv; v.y *= inv; v.z *= inv; v.w *= inv;
            }
            shX4[node * G4 + c4] = v;
        }
        __syncthreads();

        float acc[2][8];
        #pragma unroll
        for (int r = 0; r < 2; r++)
            #pragma unroll
            for (int j = 0; j < 8; j++) acc[r][j] = 0.f;
        #pragma unroll 4
        for (int c4 = 0; c4 < 32; c4++) {
            float4 w0 = shW4[rg * G4 + c4];
            float4 w1 = shW4[(rg + 192) * G4 + c4];
            #pragma unroll
            for (int j = 0; j < 8; j++) {
                float4 xv = shX4[(eg * 8 + j) * G4 + c4];
                acc[0][j] = fmaf(w0.x, xv.x, acc[0][j]);
                acc[0][j] = fmaf(w0.y, xv.y, acc[0][j]);
                acc[0][j] = fmaf(w0.z, xv.z, acc[0][j]);
                acc[0][j] = fmaf(w0.w, xv.w, acc[0][j]);
                acc[1][j] = fmaf(w1.x, xv.x, acc[1][j]);
                acc[1][j] = fmaf(w1.y, xv.y, acc[1][j]);
                acc[1][j] = fmaf(w1.z, xv.z, acc[1][j]);
                acc[1][j] = fmaf(w1.w, xv.w, acc[1][j]);
            }
        }
        #pragma unroll
        for (int j = 0; j < 8; j++) {
            size_t base = (size_t)(n0 + eg * 8 + j) * GOUT;
            y[base + rg]       = acc[0][j] + b0;
            y[base + rg + 192] = acc[1][j] + b1;
        }
        __syncthreads();
    }
}

// ============================================================
__global__ void k_comb(const float* __restrict__ mem, float* __restrict__ out) {
    size_t i = (size_t)blockIdx.x * blockDim.x + threadIdx.x;
    size_t stride = (size_t)gridDim.x * blockDim.x;
    for (size_t i4 = i; i4 < (size_t)NN * 32; i4 += stride) {
        size_t n = i4 >> 5; int q = (int)(i4 & 31);
        size_t gb = n * 96 + q;
        float4 ir = ((const float4*)g_gi)[gb];
        float4 iz = ((const float4*)g_gi)[gb + 32];
        float4 in_ = ((const float4*)g_gi)[gb + 64];
        float4 hr = ((const float4*)g_gh)[gb];
        float4 hz = ((const float4*)g_gh)[gb + 32];
        float4 hn = ((const float4*)g_gh)[gb + 64];
        float4 m = ((const float4*)mem)[i4];
        float4 o;
        { float rg = 1.f/(1.f+expf(-(ir.x+hr.x))), zg = 1.f/(1.f+expf(-(iz.x+hz.x)));
          o.x = (1.f-zg)*tanhf(in_.x+rg*hn.x) + zg*m.x; }
        { float rg = 1.f/(1.f+expf(-(ir.y+hr.y))), zg = 1.f/(1.f+expf(-(iz.y+hz.y)));
          o.y = (1.f-zg)*tanhf(in_.y+rg*hn.y) + zg*m.y; }
        { float rg = 1.f/(1.f+expf(-(ir.z+hr.z))), zg = 1.f/(1.f+expf(-(iz.z+hz.z)));
          o.z = (1.f-zg)*tanhf(in_.z+rg*hn.z) + zg*m.z; }
        { float rg = 1.f/(1.f+expf(-(ir.w+hr.w))), zg = 1.f/(1.f+expf(-(iz.w+hz.w)));
          o.w = (1.f-zg)*tanhf(in_.w+rg*hn.w) + zg*m.w; }
        ((float4*)out)[i4] = o;
    }
}

// ============================================================
__global__ void k_lu(float* __restrict__ out) {
    int i = blockIdx.x * blockDim.x + threadIdx.x;
    if (i < NN)
        out[(size_t)NN * DD + i] = (g_cnt[i] > 0.f) ? (float)g_tmax[i] : 0.f;
}

// ============================================================
extern "C" void kernel_launch(void* const* d_in, const int* in_sizes, int n_in,
                              void* d_out, int out_size)
{
    const float* mem = (const float*)d_in[0];
    const float* raw = (const float*)d_in[1];
    const float* tw  = (const float*)d_in[2];
    const float* tb  = (const float*)d_in[3];
    const float* Ws  = (const float*)d_in[4];
    const float* bs  = (const float*)d_in[5];
    const float* Wd  = (const float*)d_in[6];
    const float* bd  = (const float*)d_in[7];
    const float* Wih = (const float*)d_in[8];
    const float* Whh = (const float*)d_in[9];
    const float* bih = (const float*)d_in[10];
    const float* bhh = (const float*)d_in[11];
    const int* src = (const int*)d_in[12];
    const int* dst = (const int*)d_in[13];
    const int* tt  = (const int*)d_in[14];
    const int* lu  = (const int*)d_in[15];
    float* out = (float*)d_out;

    float* d_gi; cudaGetSymbolAddress((void**)&d_gi, g_gi);
    float* d_gh; cudaGetSymbolAddress((void**)&d_gh, g_gh);
    float* d_sums; cudaGetSymbolAddress((void**)&d_sums, g_sums);

    size_t smem_gru = (size_t)(GOUT * GP + NT * GP) * sizeof(float);

    cudaFuncSetAttribute(k_msgT, cudaFuncAttributeMaxDynamicSharedMemorySize, SMEM_MSG);
    cudaFuncSetAttribute(k_gemm, cudaFuncAttributeMaxDynamicSharedMemorySize, (int)smem_gru);

    k_init<<<2048, 256>>>();
    k_msgT<<<2 * NB, 256, SMEM_MSG>>>(mem, raw, tw, tb, Ws, bs, Wd, bd, src, dst, tt, lu);
    k_gemm<<<NB, 768, smem_gru>>>(Wih, bih, d_sums, 1, d_gi);
    k_gemm<<<NB, 768, smem_gru>>>(Whh, bhh, mem, 0, d_gh);
    k_comb<<<2048, 256>>>(mem, out);
    if (out_size >= NN * DD + NN)
        k_lu<<<(NN + 255) / 256, 256>>>(out);
}